// round 1
// baseline (speedup 1.0000x reference)
#include <cuda_runtime.h>

// Restricted self-attention, restructured:
//   scores affine in x  ->  softmax weights w_i = exp(a_h * x_i) / Z
//   gaussian_basis is effectively ~30-nonzeros-per-column sparse (fp32-exact zeros
//   beyond |j - mu_i| > 0.449), so ctx[b,j] = sum_{i in window(j)} w_i * x_i * G[i,j]
//   then per-batch descending sort of 256 values.

#define SEQ   8192
#define BATCH 64
#define HID   256

__device__ float g_ctx[BATCH * HID];

__device__ __forceinline__ float ex2f_(float x) {
    float r;
    asm("ex2.approx.ftz.f32 %0, %1;" : "=f"(r) : "f"(x));
    return r;
}

// grid (64, 2): block (b, s) handles batch b, heads [s*4, s*4+4), output cols [s*128, s*128+128)
__global__ __launch_bounds__(256) void attn_main(
    const float* __restrict__ x_all,   // (64, 8192, 1)
    const float* __restrict__ qw,      // (128,)
    const float* __restrict__ qb,      // (128,)
    const float* __restrict__ kw,      // (128,)
    const float* __restrict__ G)       // (8192, 256)
{
    __shared__ float sx[SEQ];
    __shared__ float s_wmax[8], s_wmin[8];
    __shared__ float s_ext[2];         // xmax, xmin over this batch
    __shared__ float s_a[4], s_m[4], s_Z[4];
    __shared__ float s_zp[8][4];

    const int b    = blockIdx.x;
    const int sgrp = blockIdx.y;       // 0 or 1
    const int tid  = threadIdx.x;
    const int wid  = tid >> 5;
    const int lane = tid & 31;

    const float* x = x_all + b * SEQ;

    // ---- load x into shared, fused max/min reduction ----
    float mx = -3.4e38f, mn = 3.4e38f;
    const float4* x4  = reinterpret_cast<const float4*>(x);
    float4*       sx4 = reinterpret_cast<float4*>(sx);
#pragma unroll
    for (int it = 0; it < (SEQ / 4) / 256; ++it) {
        int idx = tid + it * 256;
        float4 v = x4[idx];
        sx4[idx] = v;
        mx = fmaxf(mx, fmaxf(fmaxf(v.x, v.y), fmaxf(v.z, v.w)));
        mn = fminf(mn, fminf(fminf(v.x, v.y), fminf(v.z, v.w)));
    }
#pragma unroll
    for (int o = 16; o > 0; o >>= 1) {
        mx = fmaxf(mx, __shfl_xor_sync(0xffffffffu, mx, o));
        mn = fminf(mn, __shfl_xor_sync(0xffffffffu, mn, o));
    }
    if (lane == 0) { s_wmax[wid] = mx; s_wmin[wid] = mn; }
    __syncthreads();
    if (tid == 0) {
        float M = s_wmax[0], N = s_wmin[0];
#pragma unroll
        for (int w = 1; w < 8; ++w) { M = fmaxf(M, s_wmax[w]); N = fminf(N, s_wmin[w]); }
        s_ext[0] = M; s_ext[1] = N;
    }
    __syncthreads();

    // ---- per-head affine slope a_h (C_h cancels in softmax) + stability shift m ----
    if (tid < 4) {
        int   h   = sgrp * 4 + tid;
        float x0  = sx[0];
        float acc = 0.f;
        int   base = h * 16;
#pragma unroll
        for (int d = 0; d < 16; ++d)
            acc += (x0 * qw[base + d] + qb[base + d]) * kw[base + d];
        float a  = acc * 0.17677669529663687f;     // 1/sqrt(32)
        float al = a * 1.4426950408889634f;        // to log2 units
        s_a[tid] = al;
        s_m[tid] = al * ((al > 0.f) ? s_ext[0] : s_ext[1]);
    }
    __syncthreads();

    const float a0 = s_a[0], a1 = s_a[1], a2 = s_a[2], a3 = s_a[3];
    const float m0 = s_m[0], m1 = s_m[1], m2 = s_m[2], m3 = s_m[3];

    // ---- softmax denominators Z (full sum over SEQ, 4 heads) ----
    float z0 = 0.f, z1 = 0.f, z2 = 0.f, z3 = 0.f;
#pragma unroll 4
    for (int i = tid; i < SEQ; i += 256) {
        float xv = sx[i];
        z0 += ex2f_(fmaf(a0, xv, -m0));
        z1 += ex2f_(fmaf(a1, xv, -m1));
        z2 += ex2f_(fmaf(a2, xv, -m2));
        z3 += ex2f_(fmaf(a3, xv, -m3));
    }
#pragma unroll
    for (int o = 16; o > 0; o >>= 1) {
        z0 += __shfl_xor_sync(0xffffffffu, z0, o);
        z1 += __shfl_xor_sync(0xffffffffu, z1, o);
        z2 += __shfl_xor_sync(0xffffffffu, z2, o);
        z3 += __shfl_xor_sync(0xffffffffu, z3, o);
    }
    if (lane == 0) {
        s_zp[wid][0] = z0; s_zp[wid][1] = z1;
        s_zp[wid][2] = z2; s_zp[wid][3] = z3;
    }
    __syncthreads();
    if (tid < 4) {                      // deterministic fixed-order combine
        float zz = 0.f;
#pragma unroll
        for (int w = 0; w < 8; ++w) zz += s_zp[w][tid];
        s_Z[tid] = zz;
    }
    __syncthreads();

    // ---- context via sparse window of G (G is fp32-exact zero outside |j-mu_i|>0.449) ----
    if (tid < 128) {
        int   j  = sgrp * 128 + tid;
        int   hl = tid >> 5;
        float av = s_a[hl], mv = s_m[hl];
        const float R = 8191.0f / 255.0f;   // d(i)/d(mu)
        int lo = (int)ceilf(((float)j - 0.47f) * R);
        int hi = (int)floorf(((float)j + 0.47f) * R);
        if (lo < 0) lo = 0;
        if (hi > SEQ - 1) hi = SEQ - 1;
        float acc = 0.f;
        for (int i = lo; i <= hi; ++i) {
            float g  = __ldg(&G[i * HID + j]);
            float xv = sx[i];
            acc = fmaf(ex2f_(fmaf(av, xv, -mv)) * xv, g, acc);
        }
        g_ctx[b * HID + j] = acc / s_Z[hl];
    }
}

// grid 64: per-batch bitonic sort (descending) of the 256 context values
__global__ __launch_bounds__(256) void sort_out(float* __restrict__ out) {
    __shared__ float sv[HID];
    int b = blockIdx.x, tid = threadIdx.x;
    sv[tid] = g_ctx[b * HID + tid];
    __syncthreads();
    for (int k = 2; k <= HID; k <<= 1) {
        for (int jj = k >> 1; jj > 0; jj >>= 1) {
            int ixj = tid ^ jj;
            if (ixj > tid) {
                float A = sv[tid], B = sv[ixj];
                if ((A < B) == ((tid & k) == 0)) { sv[tid] = B; sv[ixj] = A; }
            }
            __syncthreads();
        }
    }
    out[b * HID + tid] = sv[tid];
}

extern "C" void kernel_launch(void* const* d_in, const int* in_sizes, int n_in,
                              void* d_out, int out_size) {
    const float* x  = (const float*)d_in[0];   // input_tensor (64,8192,1)
    const float* qw = (const float*)d_in[1];   // q_w (128,1)
    const float* qb = (const float*)d_in[2];   // q_b (128,)
    const float* kw = (const float*)d_in[3];   // k_w (128,1)
    // d_in[4] = k_b: cancels in softmax, unused
    const float* G  = (const float*)d_in[5];   // gaussian_basis (8192,256)
    float* out = (float*)d_out;

    dim3 grid1(BATCH, 2);
    attn_main<<<grid1, 256>>>(x, qw, qb, kw, G);
    sort_out<<<BATCH, 256>>>(out);
}

// round 2
// speedup vs baseline: 1.0172x; 1.0172x over previous
#include <cuda_runtime.h>

// Fully fused restricted self-attention:
//   scores affine in x  ->  softmax weights w_i = exp(a_h * x_i - m_h) / Z_h
//   gaussian_basis G is fp32-exact zero beyond |j - mu_i| > 0.449 -> ctx is a
//   ~30-row windowed dot per output column
//   per-batch descending sort done in-block (shfl bitonic).
// One kernel, grid 64 (one block per batch), 256 threads.

#define SEQ   8192
#define BATCH 64
#define HID   256

typedef unsigned long long u64;

__device__ __forceinline__ float ex2f_(float x) {
    float r; asm("ex2.approx.ftz.f32 %0, %1;" : "=f"(r) : "f"(x)); return r;
}
__device__ __forceinline__ u64 pack2(float lo, float hi) {
    u64 r; asm("mov.b64 %0, {%1, %2};" : "=l"(r) : "f"(lo), "f"(hi)); return r;
}
__device__ __forceinline__ float lo2(u64 v) {
    float f; asm("{.reg .f32 h; mov.b64 {%0, h}, %1;}" : "=f"(f) : "l"(v)); return f;
}
__device__ __forceinline__ float hi2(u64 v) {
    float f; asm("{.reg .f32 l; mov.b64 {l, %0}, %1;}" : "=f"(f) : "l"(v)); return f;
}
__device__ __forceinline__ u64 fma2_(u64 a, u64 b, u64 c) {
    u64 d; asm("fma.rn.f32x2 %0, %1, %2, %3;" : "=l"(d) : "l"(a), "l"(b), "l"(c)); return d;
}
__device__ __forceinline__ u64 add2_(u64 a, u64 b) {
    u64 d; asm("add.rn.f32x2 %0, %1, %2;" : "=l"(d) : "l"(a), "l"(b)); return d;
}

// packed exp2 of two non-positive floats via FMA-pipe polynomial (t <= 0 guaranteed)
__device__ __forceinline__ u64 exp2_poly2(u64 t2, u64 C2, u64 NC2, u64 M1_2) {
    u64 k2 = add2_(t2, C2);                 // round-to-nearest int in mantissa bits
    u64 s2 = add2_(k2, NC2);                // s = rint(t)
    u64 f2 = fma2_(s2, M1_2, t2);           // f = t - s,  f in [-0.5, 0.5]
    u64 p2 = fma2_(f2, pack2(0.00961804696f, 0.00961804696f),
                       pack2(0.0555041086f, 0.0555041086f));
    p2 = fma2_(f2, p2, pack2(0.240226507f, 0.240226507f));
    p2 = fma2_(f2, p2, pack2(0.693147182f, 0.693147182f));
    p2 = fma2_(f2, p2, pack2(1.0f, 1.0f));
    // 2^n scale via exponent-bit add; ki = 0x4B400000 + n, (ki<<23) == (n<<23)
    int ki_lo = (int)(unsigned)(k2);
    int ki_hi = (int)(unsigned)(k2 >> 32);
    ki_lo = max(ki_lo, 0x4B3FFF92);         // clamp n >= -110 (underflow guard)
    ki_hi = max(ki_hi, 0x4B3FFF92);
    float e_lo = __int_as_float(__float_as_int(lo2(p2)) + (ki_lo << 23));
    float e_hi = __int_as_float(__float_as_int(hi2(p2)) + (ki_hi << 23));
    return pack2(e_lo, e_hi);
}

__global__ __launch_bounds__(256) void attn_fused(
    const float* __restrict__ x_all,   // (64, 8192, 1)
    const float* __restrict__ qw,      // (128,)
    const float* __restrict__ qb,      // (128,)
    const float* __restrict__ kw,      // (128,)
    const float* __restrict__ G,       // (8192, 256)
    float* __restrict__ out)           // (64, 1, 256)
{
    __shared__ __align__(16) float sx[SEQ];
    __shared__ float s_wmax[8], s_wmin[8];
    __shared__ float s_ext[2];
    __shared__ float s_a[8], s_m[8], s_Z[8];
    __shared__ float s_zp[8][8];
    __shared__ float s_ctx[HID];

    const int b    = blockIdx.x;
    const int tid  = threadIdx.x;
    const int wid  = tid >> 5;
    const int lane = tid & 31;

    const float* x = x_all + b * SEQ;

    // ---- Phase A: load x -> shared (float4), fused min/max ----
    float mx = -3.4e38f, mn = 3.4e38f;
    {
        const float4* x4  = reinterpret_cast<const float4*>(x);
        float4*       sx4 = reinterpret_cast<float4*>(sx);
#pragma unroll
        for (int it = 0; it < (SEQ / 4) / 256; ++it) {
            int idx = tid + it * 256;
            float4 v = x4[idx];
            sx4[idx] = v;
            mx = fmaxf(mx, fmaxf(fmaxf(v.x, v.y), fmaxf(v.z, v.w)));
            mn = fminf(mn, fminf(fminf(v.x, v.y), fminf(v.z, v.w)));
        }
    }
#pragma unroll
    for (int o = 16; o > 0; o >>= 1) {
        mx = fmaxf(mx, __shfl_xor_sync(0xffffffffu, mx, o));
        mn = fminf(mn, __shfl_xor_sync(0xffffffffu, mn, o));
    }
    if (lane == 0) { s_wmax[wid] = mx; s_wmin[wid] = mn; }
    __syncthreads();
    if (tid == 0) {
        float M = s_wmax[0], N = s_wmin[0];
#pragma unroll
        for (int w = 1; w < 8; ++w) { M = fmaxf(M, s_wmax[w]); N = fminf(N, s_wmin[w]); }
        s_ext[0] = M; s_ext[1] = N;
    }
    __syncthreads();

    // ---- Phase B: per-head slope a_h (log2 units) and stability shift m_h ----
    if (tid < 8) {
        float x0  = sx[0];
        float acc = 0.f;
        int   base = tid * 16;
#pragma unroll
        for (int d = 0; d < 16; ++d)
            acc += (x0 * qw[base + d] + qb[base + d]) * kw[base + d];
        float a  = acc * 0.17677669529663687f;   // 1/sqrt(32)
        float al = a * 1.4426950408889634f;      // log2(e)
        s_a[tid] = al;
        s_m[tid] = al * ((al > 0.f) ? s_ext[0] : s_ext[1]);  // ensures t <= 0
    }
    __syncthreads();

    // ---- Phase C: softmax denominators Z for 8 heads, packed f32x2 ----
    // heads 0..4 via MUFU ex2, heads 5..7 via FMA-pipe poly (pipe balancing)
    {
        u64 A[8], NM[8], Z2[8];
#pragma unroll
        for (int h = 0; h < 8; ++h) {
            float a = s_a[h], m = s_m[h];
            A[h]  = pack2(a, a);
            NM[h] = pack2(-m, -m);
            Z2[h] = 0ull;
        }
        const u64 C2   = pack2(12582912.f, 12582912.f);
        const u64 NC2  = pack2(-12582912.f, -12582912.f);
        const u64 M1_2 = pack2(-1.f, -1.f);
        const u64* sx2 = reinterpret_cast<const u64*>(sx);
#pragma unroll 2
        for (int it = 0; it < (SEQ / 2) / 256; ++it) {
            u64 x2 = sx2[tid + it * 256];
#pragma unroll
            for (int h = 0; h < 5; ++h) {          // MUFU heads
                u64 t2 = fma2_(A[h], x2, NM[h]);
                float e0 = ex2f_(lo2(t2));
                float e1 = ex2f_(hi2(t2));
                Z2[h] = add2_(Z2[h], pack2(e0, e1));
            }
#pragma unroll
            for (int h = 5; h < 8; ++h) {          // poly heads
                u64 t2 = fma2_(A[h], x2, NM[h]);
                Z2[h] = add2_(Z2[h], exp2_poly2(t2, C2, NC2, M1_2));
            }
        }
#pragma unroll
        for (int h = 0; h < 8; ++h) {
            float z = lo2(Z2[h]) + hi2(Z2[h]);
#pragma unroll
            for (int o = 16; o > 0; o >>= 1)
                z += __shfl_xor_sync(0xffffffffu, z, o);
            if (lane == 0) s_zp[wid][h] = z;
        }
    }
    __syncthreads();
    if (tid < 8) {                                  // fixed-order combine
        float zz = 0.f;
#pragma unroll
        for (int w = 0; w < 8; ++w) zz += s_zp[w][tid];
        s_Z[tid] = zz;
    }
    __syncthreads();

    // ---- Phase D: context via sparse window of G (one thread per column) ----
    {
        int   j  = tid;
        int   h  = tid >> 5;
        float av = s_a[h], nm = -s_m[h];
        const float R = 8191.0f / 255.0f;
        int lo = (int)ceilf(((float)j - 0.47f) * R);
        int hi = (int)floorf(((float)j + 0.47f) * R);
        if (lo < 0) lo = 0;
        if (hi > SEQ - 1) hi = SEQ - 1;
        float acc = 0.f;
        for (int i = lo; i <= hi; ++i) {
            float g  = __ldg(&G[i * HID + j]);
            float xv = sx[i];
            acc = fmaf(ex2f_(fmaf(av, xv, nm)) * xv, g, acc);
        }
        s_ctx[j] = acc / s_Z[h];
    }
    __syncthreads();

    // ---- Phase E: descending bitonic sort of 256 values, register-resident ----
    {
        float v = s_ctx[tid];
#pragma unroll
        for (int k = 2; k <= HID; k <<= 1) {
#pragma unroll
            for (int j = k >> 1; j > 0; j >>= 1) {
                float vp;
                if (j >= 32) {
                    __syncthreads();
                    s_ctx[tid] = v;
                    __syncthreads();
                    vp = s_ctx[tid ^ j];
                } else {
                    vp = __shfl_xor_sync(0xffffffffu, v, j);
                }
                bool big = ((tid & k) == 0) == ((tid & j) == 0);
                v = big ? fmaxf(v, vp) : fminf(v, vp);
            }
        }
        out[b * HID + tid] = v;
    }
}

extern "C" void kernel_launch(void* const* d_in, const int* in_sizes, int n_in,
                              void* d_out, int out_size) {
    const float* x  = (const float*)d_in[0];   // input_tensor (64,8192,1)
    const float* qw = (const float*)d_in[1];   // q_w (128,1)
    const float* qb = (const float*)d_in[2];   // q_b (128,)
    const float* kw = (const float*)d_in[3];   // k_w (128,1)
    // d_in[4] = k_b: cancels in softmax, unused
    const float* G  = (const float*)d_in[5];   // gaussian_basis (8192,256)
    float* out = (float*)d_out;

    attn_fused<<<BATCH, 256>>>(x, qw, qb, kw, G, out);
}